// round 1
// baseline (speedup 1.0000x reference)
#include <cuda_runtime.h>
#include <math.h>

// Problem constants
#define B_    16384
#define F_    64
#define H_    512
#define C_    512
#define NBINS 30
#define MULT_ 91            // 3*NBINS+1
#define NOUT  (F_*MULT_)    // 5824
#define NBLK  3

// ----------------------------------------------------------------------------
// Device scratch (no allocations allowed)
// ----------------------------------------------------------------------------
__device__ float g_WinM [F_*H_];
__device__ float g_WhhM [2*NBLK*H_*H_];     // [0..2]=Wb1 masked, [3..5]=Wb2 masked
__device__ float g_WoutM[H_*NOUT];
__device__ float g_t[B_*H_];
__device__ float g_u[B_*H_];
__device__ float g_v[B_*H_];
__device__ float g_g[B_*H_];
__device__ float g_P[(size_t)B_*NOUT];

// ----------------------------------------------------------------------------
// Mask prep kernels (MADE degree masks, applied to weights once per launch)
// d_h[j] = j % (F-1) + 1
// ----------------------------------------------------------------------------
__global__ void mask_in_kernel(const float* __restrict__ W, float* __restrict__ out) {
    int x = blockIdx.x * blockDim.x + threadIdx.x;
    if (x >= F_*H_) return;
    int f = x / H_, j = x % H_;
    int dh = j % (F_-1) + 1;
    out[x] = (dh >= f + 1) ? W[x] : 0.f;
}

__global__ void mask_hh_kernel(const float* __restrict__ W, float* __restrict__ out, int total) {
    int x = blockIdx.x * blockDim.x + threadIdx.x;
    if (x >= total) return;
    int ij = x % (H_*H_);
    int i = ij / H_, j = ij % H_;
    int di = i % (F_-1) + 1, dj = j % (F_-1) + 1;
    out[x] = (dj >= di) ? W[x] : 0.f;
}

__global__ void mask_out_kernel(const float* __restrict__ W, float* __restrict__ out) {
    int x = blockIdx.x * blockDim.x + threadIdx.x;
    if (x >= H_*NOUT) return;
    int j = x / NOUT, k = x % NOUT;
    int dj   = j % (F_-1) + 1;
    int dout = k / MULT_ + 1;
    out[x] = (dout > dj) ? W[x] : 0.f;
}

// ----------------------------------------------------------------------------
// Tiled fp32 SGEMM: C[M,N] = op(A[M,K]) @ W[K,N] (+ bias) (+ C)
// BM=BN=64, BK=16, 256 threads, 4x4 micro-tile per thread.
// All problem dims are multiples of tile sizes -> no bounds checks.
// ----------------------------------------------------------------------------
#define BM 64
#define BN 64
#define BK 16

template<bool RELU_A, bool ACCUM, bool BIAS>
__global__ void sgemm_kernel(const float* __restrict__ A, const float* __restrict__ W,
                             const float* __restrict__ bias, float* __restrict__ C,
                             int M, int N, int K) {
    __shared__ float As[BK][BM];
    __shared__ float Bs[BK][BN];

    int tid = threadIdx.x;           // 0..255
    int tx = tid & 15;               // 0..15 (N dir)
    int ty = tid >> 4;               // 0..15 (M dir)
    int row0 = blockIdx.y * BM;
    int col0 = blockIdx.x * BN;

    // load mapping
    int arow = tid >> 2;             // 0..63
    int ac4  = (tid & 3) * 4;        // 0,4,8,12
    int wrow = tid >> 4;             // 0..15
    int wc4  = (tid & 15) * 4;       // 0..60

    float acc[4][4] = {};

    for (int k0 = 0; k0 < K; k0 += BK) {
        float4 a = *reinterpret_cast<const float4*>(&A[(size_t)(row0 + arow) * K + k0 + ac4]);
        if (RELU_A) {
            a.x = fmaxf(a.x, 0.f); a.y = fmaxf(a.y, 0.f);
            a.z = fmaxf(a.z, 0.f); a.w = fmaxf(a.w, 0.f);
        }
        As[ac4 + 0][arow] = a.x;
        As[ac4 + 1][arow] = a.y;
        As[ac4 + 2][arow] = a.z;
        As[ac4 + 3][arow] = a.w;

        float4 b = *reinterpret_cast<const float4*>(&W[(size_t)(k0 + wrow) * N + col0 + wc4]);
        *reinterpret_cast<float4*>(&Bs[wrow][wc4]) = b;

        __syncthreads();

        #pragma unroll
        for (int k = 0; k < BK; k++) {
            float4 ra = *reinterpret_cast<const float4*>(&As[k][ty * 4]);
            float4 rb = *reinterpret_cast<const float4*>(&Bs[k][tx * 4]);
            float raf[4] = {ra.x, ra.y, ra.z, ra.w};
            float rbf[4] = {rb.x, rb.y, rb.z, rb.w};
            #pragma unroll
            for (int i = 0; i < 4; i++)
                #pragma unroll
                for (int j = 0; j < 4; j++)
                    acc[i][j] += raf[i] * rbf[j];
        }
        __syncthreads();
    }

    #pragma unroll
    for (int i = 0; i < 4; i++) {
        int r = row0 + ty * 4 + i;
        #pragma unroll
        for (int j = 0; j < 4; j++) {
            int c = col0 + tx * 4 + j;
            float v = acc[i][j];
            if (BIAS)  v += bias[c];
            if (ACCUM) v += C[(size_t)r * N + c];
            C[(size_t)r * N + c] = v;
        }
    }
}

// ----------------------------------------------------------------------------
// Residual GLU gate: t += v * sigmoid(g)
// ----------------------------------------------------------------------------
__global__ void glu_add_kernel(float* __restrict__ t, const float* __restrict__ v,
                               const float* __restrict__ g, int n) {
    int i = blockIdx.x * blockDim.x + threadIdx.x;
    if (i >= n) return;
    float gg = g[i];
    t[i] += v[i] * (1.f / (1.f + expf(-gg)));
}

// ----------------------------------------------------------------------------
// Rational-quadratic spline + product over features.
// One block per batch row, 64 threads = one feature each.
// Matches nflows semantics: softmax -> min_bin affine -> cumsum with edge
// resets (cw[0]=0, cw[-1]=1, widths recomputed as diff), searchsorted with
// +1e-6 on the last edge, derivatives NOT scaled by 1/sqrt(H).
// ----------------------------------------------------------------------------
__device__ __forceinline__ float softplusf(float x) {
    return fmaxf(x, 0.f) + log1pf(expf(-fabsf(x)));
}

__global__ void spline_kernel(const float* __restrict__ P, const float* __restrict__ pred,
                              float* __restrict__ out) {
    int b = blockIdx.x;
    int f = threadIdx.x;   // 0..63
    const float* p = P + (size_t)b * NOUT + f * MULT_;
    float x = pred[b * F_ + f];

    float cdf;
    if (x == 1.0f) {
        cdf = 1.0f;
    } else {
        const float scale = 0.04419417382415922f;  // 1/sqrt(512)

        // widths
        float ew[NBINS];
        float mx = -1e30f;
        #pragma unroll
        for (int k = 0; k < NBINS; k++) { ew[k] = p[k] * scale; mx = fmaxf(mx, ew[k]); }
        float s = 0.f;
        #pragma unroll
        for (int k = 0; k < NBINS; k++) { ew[k] = expf(ew[k] - mx); s += ew[k]; }
        float inv = (1.f - 1e-3f * NBINS) / s;
        float cw[NBINS + 1];
        cw[0] = 0.f;
        float run = 0.f;
        #pragma unroll
        for (int k = 0; k < NBINS; k++) { run += 1e-3f + ew[k] * inv; cw[k + 1] = run; }
        cw[NBINS] = 1.f;

        // heights
        float eh[NBINS];
        mx = -1e30f;
        #pragma unroll
        for (int k = 0; k < NBINS; k++) { eh[k] = p[NBINS + k] * scale; mx = fmaxf(mx, eh[k]); }
        s = 0.f;
        #pragma unroll
        for (int k = 0; k < NBINS; k++) { eh[k] = expf(eh[k] - mx); s += eh[k]; }
        inv = (1.f - 1e-3f * NBINS) / s;
        float ch[NBINS + 1];
        ch[0] = 0.f;
        run = 0.f;
        #pragma unroll
        for (int k = 0; k < NBINS; k++) { run += 1e-3f + eh[k] * inv; ch[k + 1] = run; }
        ch[NBINS] = 1.f;

        // searchsorted: count edges <= x (last edge gets +1e-6)
        int cnt = 0;
        #pragma unroll
        for (int k = 0; k <= NBINS; k++) {
            float loc = (k == NBINS) ? (1.f + 1e-6f) : cw[k];
            cnt += (x >= loc) ? 1 : 0;
        }
        int idx = min(max(cnt - 1, 0), NBINS - 1);

        float in_cw = cw[idx], in_w = cw[idx + 1] - cw[idx];
        float in_ch = ch[idx], in_h = ch[idx + 1] - ch[idx];
        float d0 = 1e-3f + softplusf(p[2 * NBINS + idx]);
        float d1 = 1e-3f + softplusf(p[2 * NBINS + idx + 1]);

        float delta = in_h / in_w;
        float theta = (x - in_cw) / in_w;
        float tt = theta * (1.f - theta);
        float num = in_h * (delta * theta * theta + d0 * tt);
        float den = delta + (d0 + d1 - 2.f * delta) * tt;
        cdf = in_ch + num / den;
    }

    // product-reduce over 64 features (double accumulation to be robust to
    // reduction-order differences near underflow)
    double vv = (double)cdf;
    #pragma unroll
    for (int o = 16; o > 0; o >>= 1)
        vv *= __shfl_xor_sync(0xffffffffu, vv, o);

    __shared__ double sred[2];
    int w = threadIdx.x >> 5;
    if ((threadIdx.x & 31) == 0) sred[w] = vv;
    __syncthreads();
    if (threadIdx.x == 0) out[b] = (float)(sred[0] * sred[1]);
}

// ----------------------------------------------------------------------------
// Launch
// ----------------------------------------------------------------------------
extern "C" void kernel_launch(void* const* d_in, const int* in_sizes, int n_in,
                              void* d_out, int out_size) {
    const float* pred  = (const float*)d_in[0];
    const float* ctx   = (const float*)d_in[1];
    const float* W_in  = (const float*)d_in[2];
    const float* b_in  = (const float*)d_in[3];
    const float* Wc_in = (const float*)d_in[4];
    const float* bc_in = (const float*)d_in[5];
    const float* Wb1   = (const float*)d_in[6];
    const float* bb1   = (const float*)d_in[7];
    const float* Wb2   = (const float*)d_in[8];
    const float* bb2   = (const float*)d_in[9];
    const float* Wcb   = (const float*)d_in[10];
    const float* bcb   = (const float*)d_in[11];
    const float* W_out = (const float*)d_in[12];
    const float* b_out = (const float*)d_in[13];
    float* out = (float*)d_out;

    float *winm, *whhm, *woutm, *t, *u, *v, *g, *P;
    cudaGetSymbolAddress((void**)&winm,  g_WinM);
    cudaGetSymbolAddress((void**)&whhm,  g_WhhM);
    cudaGetSymbolAddress((void**)&woutm, g_WoutM);
    cudaGetSymbolAddress((void**)&t, g_t);
    cudaGetSymbolAddress((void**)&u, g_u);
    cudaGetSymbolAddress((void**)&v, g_v);
    cudaGetSymbolAddress((void**)&g, g_g);
    cudaGetSymbolAddress((void**)&P, g_P);

    const int HH = H_ * H_;

    // 1) mask weights
    mask_in_kernel <<<(F_*H_ + 255) / 256, 256>>>(W_in, winm);
    mask_hh_kernel <<<(NBLK*HH + 255) / 256, 256>>>(Wb1, whhm,            NBLK*HH);
    mask_hh_kernel <<<(NBLK*HH + 255) / 256, 256>>>(Wb2, whhm + NBLK*HH,  NBLK*HH);
    mask_out_kernel<<<(H_*NOUT + 255) / 256, 256>>>(W_out, woutm);

    // 2) t = pred @ WinM + b_in ; t += ctx @ Wc_in + bc_in
    {
        dim3 grid(H_ / BN, B_ / BM);
        sgemm_kernel<false, false, true><<<grid, 256>>>(pred, winm, b_in, t, B_, H_, F_);
        sgemm_kernel<false, true,  true><<<grid, 256>>>(ctx, Wc_in, bc_in, t, B_, H_, C_);
    }

    // 3) residual blocks
    for (int i = 0; i < NBLK; i++) {
        dim3 grid(H_ / BN, B_ / BM);
        sgemm_kernel<true,  false, true><<<grid, 256>>>(t, whhm + (size_t)i*HH,            bb1 + i*H_, u, B_, H_, H_);
        sgemm_kernel<true,  false, true><<<grid, 256>>>(u, whhm + (size_t)(NBLK + i)*HH,   bb2 + i*H_, v, B_, H_, H_);
        sgemm_kernel<false, false, true><<<grid, 256>>>(ctx, Wcb + (size_t)i*HH,           bcb + i*H_, g, B_, C_, C_);
        glu_add_kernel<<<(B_*H_ + 255) / 256, 256>>>(t, v, g, B_ * H_);
    }

    // 4) P = t @ WoutM + b_out
    {
        dim3 grid(NOUT / BN, B_ / BM);
        sgemm_kernel<false, false, true><<<grid, 256>>>(t, woutm, b_out, P, B_, NOUT, H_);
    }

    // 5) spline + product
    spline_kernel<<<B_, F_>>>(P, pred, out);
}